// round 15
// baseline (speedup 1.0000x reference)
#include <cuda_runtime.h>

#define Bx 16
#define Nx 20000
#define Kx 16
#define Lx 256
#define Hx 1024
#define NOx 60000
#define NQ (NOx / 4)   // 15000 float4 per W2 row

typedef unsigned long long ull;

// ---------------- device scratch ----------------
__device__ float d_h[Hx * Bx];                 // hidden post-relu, [k*16+b]
__device__ float d_rflat[4 * Bx * NOx];        // recon partials [ky][b][j]
__device__ __align__(256) float d_xr[Bx * Nx * 8];  // packed {x,y,z,0, rx,ry,rz,0}
__device__ float d_gflat[Bx * Nx * 4];         // grad wrt recon [b][n][4]
__device__ ull   d_gpk[NOx * 8];               // packed g pairs [j][p]
__device__ float d_ghid[Bx * Hx];              // [b][k]
__device__ float d_w1t[Hx * Lx];               // W1^T [h][l]

// ---------------- packed f32x2 helpers ----------------
static __device__ __forceinline__ ull pack2(float x, float y) {
    ull r;
    asm("mov.b64 %0,{%1,%2};" : "=l"(r) : "r"(__float_as_uint(x)), "r"(__float_as_uint(y)));
    return r;
}
static __device__ __forceinline__ void unpack2(ull v, float& x, float& y) {
    unsigned lo, hi;
    asm("mov.b64 {%0,%1},%2;" : "=r"(lo), "=r"(hi) : "l"(v));
    x = __uint_as_float(lo); y = __uint_as_float(hi);
}
static __device__ __forceinline__ ull ffma2(ull a, ull b, ull c) {
    ull d;
    asm("fma.rn.f32x2 %0,%1,%2,%3;" : "=l"(d) : "l"(a), "l"(b), "l"(c));
    return d;
}
// Blackwell 256-bit load: one instruction, one line-visit for 32 bytes
static __device__ __forceinline__ void ldg256(const float* p, float4& a, float4& b) {
    asm volatile("ld.global.v8.f32 {%0,%1,%2,%3,%4,%5,%6,%7},[%8];"
                 : "=f"(a.x), "=f"(a.y), "=f"(a.z), "=f"(a.w),
                   "=f"(b.x), "=f"(b.y), "=f"(b.z), "=f"(b.w)
                 : "l"(p));
}

// ---------------- prep + hidden fused (blocks 0..3 = hidden GEMM) ----------------
__global__ void __launch_bounds__(256) k_prep(const float* __restrict__ code,
                                              const float* __restrict__ W1,
                                              const float* __restrict__ b1,
                                              const float* __restrict__ xyz,
                                              float* __restrict__ out) {
    int t = threadIdx.x;
    if (blockIdx.x < 4) {
        __shared__ float cs[Bx * Lx];
        for (int i = t; i < Bx * Lx; i += 256) cs[i] = code[i];
        __syncthreads();
        int j = blockIdx.x * 256 + t;
        float acc[Bx];
        float bj = b1[j];
#pragma unroll
        for (int b = 0; b < Bx; b++) acc[b] = bj;
#pragma unroll 8
        for (int l = 0; l < Lx; l++) {
            float w = W1[l * Hx + j];
#pragma unroll
            for (int b = 0; b < Bx; b++) acc[b] += cs[b * Lx + l] * w;
        }
#pragma unroll
        for (int b = 0; b < Bx; b++) d_h[j * Bx + b] = fmaxf(acc[b], 0.f);
        return;
    }
    int i = (blockIdx.x - 4) * 256 + t;
    if (i < Bx * Nx * 4) d_gflat[i] = 0.f;
    if (i < Bx * Nx) {
        float4 v;
        v.x = xyz[i * 3 + 0]; v.y = xyz[i * 3 + 1]; v.z = xyz[i * 3 + 2]; v.w = 0.f;
        ((float4*)d_xr)[i * 2] = v;
    }
    if (i < Lx * Hx) { int l = i >> 10, h = i & 1023; d_w1t[h * Lx + l] = W1[i]; }
    if (i < Bx * Hx) d_ghid[i] = 0.f;
    if (i < Bx + Bx * Lx) out[i] = 0.f;
}

// ---------------- recon partials: grid (4 ky, 74 q-blocks), exact work ----------------
__global__ void __launch_bounds__(256, 2) k_recon(const float* __restrict__ W2) {
    __shared__ __align__(16) float hs[256 * 16];  // 16 KB h chunk [k][b]
    int t = threadIdx.x;
    int ky = blockIdx.x;
    for (int i = t; i < 256 * 16; i += 256) hs[i] = d_h[ky * 256 * 16 + i];
    __syncthreads();
    int q = blockIdx.y * 256 + t;
    if (q >= NQ) return;
    const ulonglong2* hu = (const ulonglong2*)hs;
    const float4* wq = ((const float4*)W2) + (size_t)(ky * 256) * NQ;
    ull acc[4][8];
#pragma unroll
    for (int jj = 0; jj < 4; jj++)
#pragma unroll
        for (int p = 0; p < 8; p++) acc[jj][p] = 0ull;

    for (int k4 = 0; k4 < 256; k4 += 4) {
        float4 w[4];
#pragma unroll
        for (int u = 0; u < 4; u++) w[u] = wq[(size_t)(k4 + u) * NQ + q];
#pragma unroll
        for (int u = 0; u < 4; u++) {
            int k = k4 + u;
            ulonglong2 ha = hu[k * 4 + 0], hb = hu[k * 4 + 1];
            ulonglong2 hc = hu[k * 4 + 2], hd = hu[k * 4 + 3];
            ull hv[8] = {ha.x, ha.y, hb.x, hb.y, hc.x, hc.y, hd.x, hd.y};
            ull w0 = pack2(w[u].x, w[u].x), w1 = pack2(w[u].y, w[u].y);
            ull w2v = pack2(w[u].z, w[u].z), w3 = pack2(w[u].w, w[u].w);
#pragma unroll
            for (int p = 0; p < 8; p++) {
                acc[0][p] = ffma2(hv[p], w0, acc[0][p]);
                acc[1][p] = ffma2(hv[p], w1, acc[1][p]);
                acc[2][p] = ffma2(hv[p], w2v, acc[2][p]);
                acc[3][p] = ffma2(hv[p], w3, acc[3][p]);
            }
        }
    }
    float* base = d_rflat + (size_t)ky * Bx * NOx + 4 * q;
#pragma unroll
    for (int p = 0; p < 8; p++) {
        float x0, y0, x1, y1, x2, y2, x3, y3;
        unpack2(acc[0][p], x0, y0);
        unpack2(acc[1][p], x1, y1);
        unpack2(acc[2][p], x2, y2);
        unpack2(acc[3][p], x3, y3);
        *(float4*)(base + (size_t)(2 * p) * NOx)     = make_float4(x0, x1, x2, x3);
        *(float4*)(base + (size_t)(2 * p + 1) * NOx) = make_float4(y0, y1, y2, y3);
    }
}

// ---------------- combine flat partials + bias -> packed xr slots 4..7 ----------------
__global__ void k_comb(const float* __restrict__ b2) {
    int i = blockIdx.x * 256 + threadIdx.x;  // b*Nx + n
    if (i >= Bx * Nx) return;
    int b = i / Nx, n = i - b * Nx;
    float x = 0.f, y = 0.f, z = 0.f;
#pragma unroll
    for (int ky = 0; ky < 4; ky++) {
        const float* p = d_rflat + (size_t)(ky * Bx + b) * NOx + 3 * n;
        x += p[0]; y += p[1]; z += p[2];
    }
    float4 r;
    r.x = x + b2[n * 3 + 0];
    r.y = y + b2[n * 3 + 1];
    r.z = z + b2[n * 3 + 2];
    r.w = 0.f;
    ((float4*)d_xr)[i * 2 + 1] = r;
}

// ---------------- Jacobi rotation on symmetric 4x4, compile-time (P,Q) ----------------
template <int P, int Q>
static __device__ __forceinline__ void jrot(float a[4][4], float v[4][4]) {
    float apq = a[P][Q];
    if (apq != 0.f) {
        float theta = __fdividef(0.5f * (a[Q][Q] - a[P][P]), apq);
        float tt = __fdividef(copysignf(1.f, theta), fabsf(theta) + sqrtf(theta * theta + 1.f));
        float c = rsqrtf(tt * tt + 1.f);
        float s = tt * c;
        a[P][P] -= tt * apq;
        a[Q][Q] += tt * apq;
        a[P][Q] = 0.f; a[Q][P] = 0.f;
#pragma unroll
        for (int r = 0; r < 4; r++) {
            if (r == P || r == Q) continue;
            float arp = a[r][P], arq = a[r][Q];
            float nrp = c * arp - s * arq;
            float nrq = s * arp + c * arq;
            a[r][P] = nrp; a[P][r] = nrp;
            a[r][Q] = nrq; a[Q][r] = nrq;
        }
#pragma unroll
        for (int r = 0; r < 4; r++) {
            float vrp = v[r][P], vrq = v[r][Q];
            v[r][P] = c * vrp - s * vrq;
            v[r][Q] = s * vrp + c * vrq;
        }
    }
}

// ---------------- fused per-vertex ARAP: v8 gathers, shuffle energy reduce ----------------
__global__ void __launch_bounds__(128, 4) k_arap(const float* __restrict__ wmat,
                                                 const float* __restrict__ area,
                                                 const int* __restrict__ nbr,
                                                 const int* __restrict__ numnb,
                                                 float* __restrict__ out) {
    __shared__ float sh[96 * 128];  // [slot][tid]: 6 floats per nbr, 16 nbrs = 48 KB
    const float invNK = 1.f / (float)(Nx * Kx);
    int t = threadIdx.x;
    int lane = t & 31;
    int n = blockIdx.x * 128 + t;
    int b = blockIdx.y;
    float ev = 0.f;
    if (n < Nx) {
        const float* xrb = d_xr + (size_t)b * Nx * 8;
        float4 xn, rn;
        ldg256(xrb + 8 * n, xn, rn);
        int nn = numnb[n];
        const int4* nb4 = (const int4*)(nbr + n * Kx);
        const float4* wm4 = (const float4*)(wmat + n * Kx);
        int jk[Kx]; float wk[Kx];
#pragma unroll
        for (int q = 0; q < 4; q++) {
            int4 jv = nb4[q]; float4 wv = wm4[q];
            jk[q * 4 + 0] = jv.x; jk[q * 4 + 1] = jv.y; jk[q * 4 + 2] = jv.z; jk[q * 4 + 3] = jv.w;
            wk[q * 4 + 0] = (q * 4 + 0 < nn) ? wv.x : 0.f;
            wk[q * 4 + 1] = (q * 4 + 1 < nn) ? wv.y : 0.f;
            wk[q * 4 + 2] = (q * 4 + 2 < nn) ? wv.z : 0.f;
            wk[q * 4 + 3] = (q * 4 + 3 < nn) ? wv.w : 0.f;
        }
        float S00 = 0, S01 = 0, S02 = 0, S10 = 0, S11 = 0, S12 = 0, S20 = 0, S21 = 0, S22 = 0;
#pragma unroll
        for (int k = 0; k < Kx; k++) {
            float w = wk[k];
            if (w != 0.f) {
                int j = jk[k];
                float4 xj, rj;
                ldg256(xrb + 8 * j, xj, rj);   // one 256-bit gather: both vectors
                float dx = xn.x - xj.x, dy = xn.y - xj.y, dz = xn.z - xj.z;
                float cx = rn.x - rj.x, cy = rn.y - rj.y, cz = rn.z - rj.z;
                sh[(k * 6 + 0) * 128 + t] = dx; sh[(k * 6 + 1) * 128 + t] = dy; sh[(k * 6 + 2) * 128 + t] = dz;
                sh[(k * 6 + 3) * 128 + t] = cx; sh[(k * 6 + 4) * 128 + t] = cy; sh[(k * 6 + 5) * 128 + t] = cz;
                S00 += w * dx * cx; S01 += w * dx * cy; S02 += w * dx * cz;
                S10 += w * dy * cx; S11 += w * dy * cy; S12 += w * dy * cz;
                S20 += w * dz * cx; S21 += w * dz * cy; S22 += w * dz * cz;
            }
        }
        float a[4][4], v[4][4];
        a[0][0] = S00 + S11 + S22;
        a[1][1] = S00 - S11 - S22;
        a[2][2] = S11 - S00 - S22;
        a[3][3] = S22 - S00 - S11;
        a[0][1] = a[1][0] = S12 - S21;
        a[0][2] = a[2][0] = S20 - S02;
        a[0][3] = a[3][0] = S01 - S10;
        a[1][2] = a[2][1] = S01 + S10;
        a[1][3] = a[3][1] = S02 + S20;
        a[2][3] = a[3][2] = S12 + S21;
#pragma unroll
        for (int i = 0; i < 4; i++)
#pragma unroll
            for (int j2 = 0; j2 < 4; j2++) v[i][j2] = (i == j2) ? 1.f : 0.f;
#pragma unroll
        for (int sw = 0; sw < 4; sw++) {
            jrot<0, 1>(a, v); jrot<0, 2>(a, v); jrot<0, 3>(a, v);
            jrot<1, 2>(a, v); jrot<1, 3>(a, v); jrot<2, 3>(a, v);
        }
        float best = a[0][0];
        float qw = v[0][0], qx = v[1][0], qy = v[2][0], qz = v[3][0];
#pragma unroll
        for (int m = 1; m < 4; m++)
            if (a[m][m] > best) {
                best = a[m][m];
                qw = v[0][m]; qx = v[1][m]; qy = v[2][m]; qz = v[3][m];
            }
        float inv = rsqrtf(qw * qw + qx * qx + qy * qy + qz * qz);
        qw *= inv; qx *= inv; qy *= inv; qz *= inv;
        float R00 = 1.f - 2.f * (qy * qy + qz * qz);
        float R01 = 2.f * (qx * qy - qw * qz);
        float R02 = 2.f * (qx * qz + qw * qy);
        float R10 = 2.f * (qx * qy + qw * qz);
        float R11 = 1.f - 2.f * (qx * qx + qz * qz);
        float R12 = 2.f * (qy * qz - qw * qx);
        float R20 = 2.f * (qx * qz - qw * qy);
        float R21 = 2.f * (qy * qz + qw * qx);
        float R22 = 1.f - 2.f * (qx * qx + qy * qy);

        float an = area[n];
        float coef = 2.f * an * invNK;
        float gx = 0.f, gy = 0.f, gz = 0.f, es = 0.f;
        float4* gb4 = ((float4*)d_gflat) + (size_t)b * Nx;
#pragma unroll
        for (int k = 0; k < Kx; k++) {
            float w = wk[k];
            if (w != 0.f) {
                float dx = sh[(k * 6 + 0) * 128 + t], dy = sh[(k * 6 + 1) * 128 + t], dz = sh[(k * 6 + 2) * 128 + t];
                float cx = sh[(k * 6 + 3) * 128 + t], cy = sh[(k * 6 + 4) * 128 + t], cz = sh[(k * 6 + 5) * 128 + t];
                float r0 = cx - (R00 * dx + R01 * dy + R02 * dz);
                float r1 = cy - (R10 * dx + R11 * dy + R12 * dz);
                float r2 = cz - (R20 * dx + R21 * dy + R22 * dz);
                es += w * (r0 * r0 + r1 * r1 + r2 * r2);
                float g0 = coef * w * r0, g1 = coef * w * r1, g2 = coef * w * r2;
                gx += g0; gy += g1; gz += g2;
                atomicAdd(&gb4[jk[k]], make_float4(-g0, -g1, -g2, 0.f));
            }
        }
        atomicAdd(&gb4[n], make_float4(gx, gy, gz, 0.f));
        ev = an * es * invNK;
    }
    // warp shuffle reduce, one atomic per warp
#pragma unroll
    for (int off = 16; off > 0; off >>= 1) ev += __shfl_xor_sync(0xFFFFFFFFu, ev, off);
    if (lane == 0) atomicAdd(&out[b], ev);
}

// ---------------- pack g pairs [j][p] for the backward GEMM ----------------
__global__ void k_gpack() {
    int idx = blockIdx.x * 256 + threadIdx.x;
    if (idx >= NOx * 8) return;
    int j = idx >> 3, p = idx & 7;
    int n = j / 3, c = j - 3 * n;
    float v0 = d_gflat[((size_t)(2 * p) * Nx + n) * 4 + c];
    float v1 = d_gflat[((size_t)(2 * p + 1) * Nx + n) * 4 + c];
    d_gpk[idx] = pack2(v0, v1);
}

// ---------------- g_h = g_flat @ W2^T: no smem, direct packed g loads ----------------
__global__ void __launch_bounds__(256) k_gh(const float* __restrict__ W2) {
    int t = threadIdx.x;
    int lane = t & 31, wrp = t >> 5;
    int k0 = blockIdx.x * 32 + wrp * 4;
    ull acc[4][8];
#pragma unroll
    for (int u = 0; u < 4; u++)
#pragma unroll
        for (int p = 0; p < 8; p++) acc[u][p] = 0ull;

    for (int jb = blockIdx.y * 256; jb < NOx; jb += gridDim.y * 256) {
#pragma unroll 1
        for (int s = 0; s < 8; s++) {
            int j = jb + s * 32 + lane;
            int jc = min(j, NOx - 1);
            bool valid = j < NOx;
            const ulonglong2* gp = (const ulonglong2*)(d_gpk + (size_t)jc * 8);
            ulonglong2 g01 = gp[0], g23 = gp[1], g45 = gp[2], g67 = gp[3];
            ull g[8] = {g01.x, g01.y, g23.x, g23.y, g45.x, g45.y, g67.x, g67.y};
            const float* wp = W2 + jc;
            float w[4];
#pragma unroll
            for (int u = 0; u < 4; u++) w[u] = valid ? wp[(size_t)(k0 + u) * NOx] : 0.f;
#pragma unroll
            for (int u = 0; u < 4; u++) {
                ull wpk = pack2(w[u], w[u]);
#pragma unroll
                for (int p = 0; p < 8; p++) acc[u][p] = ffma2(g[p], wpk, acc[u][p]);
            }
        }
    }
#pragma unroll
    for (int u = 0; u < 4; u++)
#pragma unroll
        for (int p = 0; p < 8; p++) {
            float x, y;
            unpack2(acc[u][p], x, y);
#pragma unroll
            for (int off = 16; off > 0; off >>= 1) {
                x += __shfl_xor_sync(0xFFFFFFFFu, x, off);
                y += __shfl_xor_sync(0xFFFFFFFFu, y, off);
            }
            if (lane == 0) {
                atomicAdd(&d_ghid[(2 * p) * Hx + k0 + u], x);
                atomicAdd(&d_ghid[(2 * p + 1) * Hx + k0 + u], y);
            }
        }
}

// ---------------- code_grad = (g_h * relu') @ W1^T ----------------
__global__ void __launch_bounds__(256) k_cgrad(float* __restrict__ out) {
    __shared__ float mg[128];
    int b = blockIdx.x, hg = blockIdx.y, t = threadIdx.x;
    if (t < 128) {
        int h = hg * 128 + t;
        mg[t] = d_ghid[b * Hx + h] * (d_h[h * Bx + b] > 0.f ? 1.f : 0.f);
    }
    __syncthreads();
    float acc = 0.f;
#pragma unroll 8
    for (int hh = 0; hh < 128; hh++) acc += mg[hh] * d_w1t[(hg * 128 + hh) * Lx + t];
    atomicAdd(&out[Bx + b * Lx + t], acc);
}

// ---------------- launch ----------------
extern "C" void kernel_launch(void* const* d_in, const int* in_sizes, int n_in,
                              void* d_out, int out_size) {
    const float* code = (const float*)d_in[0];
    const float* W1   = (const float*)d_in[1];
    const float* b1   = (const float*)d_in[2];
    const float* W2   = (const float*)d_in[3];
    const float* b2   = (const float*)d_in[4];
    const float* xyz  = (const float*)d_in[5];
    const float* wmat = (const float*)d_in[6];
    const float* area = (const float*)d_in[7];
    const int*   nbr  = (const int*)d_in[8];
    const int*   nnb  = (const int*)d_in[9];
    float* out = (float*)d_out;

    k_prep<<<4 + (Bx * Nx * 4 + 255) / 256, 256>>>(code, W1, b1, xyz, out);
    k_recon<<<dim3(4, 74), 256>>>(W2);
    k_comb<<<(Bx * Nx + 255) / 256, 256>>>(b2);
    k_arap<<<dim3((Nx + 127) / 128, Bx), 128>>>(wmat, area, nbr, nnb, out);
    k_gpack<<<(NOx * 8 + 255) / 256, 256>>>();
    k_gh<<<dim3(32, 9), 256>>>(W2);
    k_cgrad<<<dim3(Bx, 8), 256>>>(out);
    (void)in_sizes; (void)n_in; (void)out_size;
}

// round 16
// speedup vs baseline: 1.0873x; 1.0873x over previous
#include <cuda_runtime.h>

#define Bx 16
#define Nx 20000
#define Kx 16
#define Lx 256
#define Hx 1024
#define NOx 60000
#define NQ (NOx / 4)    // 15000 float4 per W2 row
#define NP2 (NOx / 2)   // 30000 j-pairs

typedef unsigned long long ull;

// ---------------- device scratch ----------------
__device__ float d_h[Hx * Bx];                 // hidden post-relu, [k*16+b]
__device__ float d_rflat[4 * Bx * NOx];        // recon partials [ky][b][j]
__device__ __align__(256) float d_xr[Bx * Nx * 8];  // packed {x,y,z,0, rx,ry,rz,0}
__device__ float d_gflat[Bx * Nx * 4];         // grad wrt recon [b][n][4]
__device__ __align__(256) ull d_gpk[NOx * 8];  // packed g pairs [j][p]
__device__ float d_ghid[Bx * Hx];              // [b][k]
__device__ float d_w1t[Hx * Lx];               // W1^T [h][l]

// ---------------- packed f32x2 helpers ----------------
static __device__ __forceinline__ ull pack2(float x, float y) {
    ull r;
    asm("mov.b64 %0,{%1,%2};" : "=l"(r) : "r"(__float_as_uint(x)), "r"(__float_as_uint(y)));
    return r;
}
static __device__ __forceinline__ void unpack2(ull v, float& x, float& y) {
    unsigned lo, hi;
    asm("mov.b64 {%0,%1},%2;" : "=r"(lo), "=r"(hi) : "l"(v));
    x = __uint_as_float(lo); y = __uint_as_float(hi);
}
static __device__ __forceinline__ ull ffma2(ull a, ull b, ull c) {
    ull d;
    asm("fma.rn.f32x2 %0,%1,%2,%3;" : "=l"(d) : "l"(a), "l"(b), "l"(c));
    return d;
}
// Blackwell 256-bit load
static __device__ __forceinline__ void ldg256(const float* p, float4& a, float4& b) {
    asm volatile("ld.global.v8.f32 {%0,%1,%2,%3,%4,%5,%6,%7},[%8];"
                 : "=f"(a.x), "=f"(a.y), "=f"(a.z), "=f"(a.w),
                   "=f"(b.x), "=f"(b.y), "=f"(b.z), "=f"(b.w)
                 : "l"(p));
}

// ---------------- prep + hidden fused (blocks 0..3 = hidden GEMM) ----------------
__global__ void __launch_bounds__(256) k_prep(const float* __restrict__ code,
                                              const float* __restrict__ W1,
                                              const float* __restrict__ b1,
                                              const float* __restrict__ xyz,
                                              float* __restrict__ out) {
    int t = threadIdx.x;
    if (blockIdx.x < 4) {
        __shared__ float cs[Bx * Lx];
        for (int i = t; i < Bx * Lx; i += 256) cs[i] = code[i];
        __syncthreads();
        int j = blockIdx.x * 256 + t;
        float acc[Bx];
        float bj = b1[j];
#pragma unroll
        for (int b = 0; b < Bx; b++) acc[b] = bj;
#pragma unroll 8
        for (int l = 0; l < Lx; l++) {
            float w = W1[l * Hx + j];
#pragma unroll
            for (int b = 0; b < Bx; b++) acc[b] += cs[b * Lx + l] * w;
        }
#pragma unroll
        for (int b = 0; b < Bx; b++) d_h[j * Bx + b] = fmaxf(acc[b], 0.f);
        return;
    }
    int i = (blockIdx.x - 4) * 256 + t;
    if (i < Bx * Nx * 4) d_gflat[i] = 0.f;
    if (i < Bx * Nx) {
        float4 v;
        v.x = xyz[i * 3 + 0]; v.y = xyz[i * 3 + 1]; v.z = xyz[i * 3 + 2]; v.w = 0.f;
        ((float4*)d_xr)[i * 2] = v;
    }
    if (i < Lx * Hx) { int l = i >> 10, h = i & 1023; d_w1t[h * Lx + l] = W1[i]; }
    if (i < Bx * Hx) d_ghid[i] = 0.f;
    if (i < Bx + Bx * Lx) out[i] = 0.f;
}

// ---------------- recon partials: grid (4 ky, 74 q-blocks), exact work ----------------
__global__ void __launch_bounds__(256, 2) k_recon(const float* __restrict__ W2) {
    __shared__ __align__(16) float hs[256 * 16];  // 16 KB h chunk [k][b]
    int t = threadIdx.x;
    int ky = blockIdx.x;
    for (int i = t; i < 256 * 16; i += 256) hs[i] = d_h[ky * 256 * 16 + i];
    __syncthreads();
    int q = blockIdx.y * 256 + t;
    if (q >= NQ) return;
    const ulonglong2* hu = (const ulonglong2*)hs;
    const float4* wq = ((const float4*)W2) + (size_t)(ky * 256) * NQ;
    ull acc[4][8];
#pragma unroll
    for (int jj = 0; jj < 4; jj++)
#pragma unroll
        for (int p = 0; p < 8; p++) acc[jj][p] = 0ull;

    for (int k4 = 0; k4 < 256; k4 += 4) {
        float4 w[4];
#pragma unroll
        for (int u = 0; u < 4; u++) w[u] = wq[(size_t)(k4 + u) * NQ + q];
#pragma unroll
        for (int u = 0; u < 4; u++) {
            int k = k4 + u;
            ulonglong2 ha = hu[k * 4 + 0], hb = hu[k * 4 + 1];
            ulonglong2 hc = hu[k * 4 + 2], hd = hu[k * 4 + 3];
            ull hv[8] = {ha.x, ha.y, hb.x, hb.y, hc.x, hc.y, hd.x, hd.y};
            ull w0 = pack2(w[u].x, w[u].x), w1 = pack2(w[u].y, w[u].y);
            ull w2v = pack2(w[u].z, w[u].z), w3 = pack2(w[u].w, w[u].w);
#pragma unroll
            for (int p = 0; p < 8; p++) {
                acc[0][p] = ffma2(hv[p], w0, acc[0][p]);
                acc[1][p] = ffma2(hv[p], w1, acc[1][p]);
                acc[2][p] = ffma2(hv[p], w2v, acc[2][p]);
                acc[3][p] = ffma2(hv[p], w3, acc[3][p]);
            }
        }
    }
    float* base = d_rflat + (size_t)ky * Bx * NOx + 4 * q;
#pragma unroll
    for (int p = 0; p < 8; p++) {
        float x0, y0, x1, y1, x2, y2, x3, y3;
        unpack2(acc[0][p], x0, y0);
        unpack2(acc[1][p], x1, y1);
        unpack2(acc[2][p], x2, y2);
        unpack2(acc[3][p], x3, y3);
        *(float4*)(base + (size_t)(2 * p) * NOx)     = make_float4(x0, x1, x2, x3);
        *(float4*)(base + (size_t)(2 * p + 1) * NOx) = make_float4(y0, y1, y2, y3);
    }
}

// ---------------- combine flat partials + bias -> packed xr slots 4..7 ----------------
__global__ void k_comb(const float* __restrict__ b2) {
    int i = blockIdx.x * 256 + threadIdx.x;  // b*Nx + n
    if (i >= Bx * Nx) return;
    int b = i / Nx, n = i - b * Nx;
    float x = 0.f, y = 0.f, z = 0.f;
#pragma unroll
    for (int ky = 0; ky < 4; ky++) {
        const float* p = d_rflat + (size_t)(ky * Bx + b) * NOx + 3 * n;
        x += p[0]; y += p[1]; z += p[2];
    }
    float4 r;
    r.x = x + b2[n * 3 + 0];
    r.y = y + b2[n * 3 + 1];
    r.z = z + b2[n * 3 + 2];
    r.w = 0.f;
    ((float4*)d_xr)[i * 2 + 1] = r;
}

// ---------------- Jacobi rotation on symmetric 4x4, compile-time (P,Q) ----------------
template <int P, int Q>
static __device__ __forceinline__ void jrot(float a[4][4], float v[4][4]) {
    float apq = a[P][Q];
    if (apq != 0.f) {
        float theta = __fdividef(0.5f * (a[Q][Q] - a[P][P]), apq);
        float tt = __fdividef(copysignf(1.f, theta), fabsf(theta) + sqrtf(theta * theta + 1.f));
        float c = rsqrtf(tt * tt + 1.f);
        float s = tt * c;
        a[P][P] -= tt * apq;
        a[Q][Q] += tt * apq;
        a[P][Q] = 0.f; a[Q][P] = 0.f;
#pragma unroll
        for (int r = 0; r < 4; r++) {
            if (r == P || r == Q) continue;
            float arp = a[r][P], arq = a[r][Q];
            float nrp = c * arp - s * arq;
            float nrq = s * arp + c * arq;
            a[r][P] = nrp; a[P][r] = nrp;
            a[r][Q] = nrq; a[Q][r] = nrq;
        }
#pragma unroll
        for (int r = 0; r < 4; r++) {
            float vrp = v[r][P], vrq = v[r][Q];
            v[r][P] = c * vrp - s * vrq;
            v[r][Q] = s * vrp + c * vrq;
        }
    }
}

// ---------------- fused per-vertex ARAP: v8 gathers, shuffle energy reduce ----------------
__global__ void __launch_bounds__(128, 4) k_arap(const float* __restrict__ wmat,
                                                 const float* __restrict__ area,
                                                 const int* __restrict__ nbr,
                                                 const int* __restrict__ numnb,
                                                 float* __restrict__ out) {
    __shared__ float sh[96 * 128];  // [slot][tid]: 6 floats per nbr, 16 nbrs = 48 KB
    const float invNK = 1.f / (float)(Nx * Kx);
    int t = threadIdx.x;
    int lane = t & 31;
    int n = blockIdx.x * 128 + t;
    int b = blockIdx.y;
    float ev = 0.f;
    if (n < Nx) {
        const float* xrb = d_xr + (size_t)b * Nx * 8;
        float4 xn, rn;
        ldg256(xrb + 8 * n, xn, rn);
        int nn = numnb[n];
        const int4* nb4 = (const int4*)(nbr + n * Kx);
        const float4* wm4 = (const float4*)(wmat + n * Kx);
        int jk[Kx]; float wk[Kx];
#pragma unroll
        for (int q = 0; q < 4; q++) {
            int4 jv = nb4[q]; float4 wv = wm4[q];
            jk[q * 4 + 0] = jv.x; jk[q * 4 + 1] = jv.y; jk[q * 4 + 2] = jv.z; jk[q * 4 + 3] = jv.w;
            wk[q * 4 + 0] = (q * 4 + 0 < nn) ? wv.x : 0.f;
            wk[q * 4 + 1] = (q * 4 + 1 < nn) ? wv.y : 0.f;
            wk[q * 4 + 2] = (q * 4 + 2 < nn) ? wv.z : 0.f;
            wk[q * 4 + 3] = (q * 4 + 3 < nn) ? wv.w : 0.f;
        }
        float S00 = 0, S01 = 0, S02 = 0, S10 = 0, S11 = 0, S12 = 0, S20 = 0, S21 = 0, S22 = 0;
#pragma unroll
        for (int k = 0; k < Kx; k++) {
            float w = wk[k];
            if (w != 0.f) {
                int j = jk[k];
                float4 xj, rj;
                ldg256(xrb + 8 * j, xj, rj);
                float dx = xn.x - xj.x, dy = xn.y - xj.y, dz = xn.z - xj.z;
                float cx = rn.x - rj.x, cy = rn.y - rj.y, cz = rn.z - rj.z;
                sh[(k * 6 + 0) * 128 + t] = dx; sh[(k * 6 + 1) * 128 + t] = dy; sh[(k * 6 + 2) * 128 + t] = dz;
                sh[(k * 6 + 3) * 128 + t] = cx; sh[(k * 6 + 4) * 128 + t] = cy; sh[(k * 6 + 5) * 128 + t] = cz;
                S00 += w * dx * cx; S01 += w * dx * cy; S02 += w * dx * cz;
                S10 += w * dy * cx; S11 += w * dy * cy; S12 += w * dy * cz;
                S20 += w * dz * cx; S21 += w * dz * cy; S22 += w * dz * cz;
            }
        }
        float a[4][4], v[4][4];
        a[0][0] = S00 + S11 + S22;
        a[1][1] = S00 - S11 - S22;
        a[2][2] = S11 - S00 - S22;
        a[3][3] = S22 - S00 - S11;
        a[0][1] = a[1][0] = S12 - S21;
        a[0][2] = a[2][0] = S20 - S02;
        a[0][3] = a[3][0] = S01 - S10;
        a[1][2] = a[2][1] = S01 + S10;
        a[1][3] = a[3][1] = S02 + S20;
        a[2][3] = a[3][2] = S12 + S21;
#pragma unroll
        for (int i = 0; i < 4; i++)
#pragma unroll
            for (int j2 = 0; j2 < 4; j2++) v[i][j2] = (i == j2) ? 1.f : 0.f;
#pragma unroll
        for (int sw = 0; sw < 4; sw++) {
            jrot<0, 1>(a, v); jrot<0, 2>(a, v); jrot<0, 3>(a, v);
            jrot<1, 2>(a, v); jrot<1, 3>(a, v); jrot<2, 3>(a, v);
        }
        float best = a[0][0];
        float qw = v[0][0], qx = v[1][0], qy = v[2][0], qz = v[3][0];
#pragma unroll
        for (int m = 1; m < 4; m++)
            if (a[m][m] > best) {
                best = a[m][m];
                qw = v[0][m]; qx = v[1][m]; qy = v[2][m]; qz = v[3][m];
            }
        float inv = rsqrtf(qw * qw + qx * qx + qy * qy + qz * qz);
        qw *= inv; qx *= inv; qy *= inv; qz *= inv;
        float R00 = 1.f - 2.f * (qy * qy + qz * qz);
        float R01 = 2.f * (qx * qy - qw * qz);
        float R02 = 2.f * (qx * qz + qw * qy);
        float R10 = 2.f * (qx * qy + qw * qz);
        float R11 = 1.f - 2.f * (qx * qx + qz * qz);
        float R12 = 2.f * (qy * qz - qw * qx);
        float R20 = 2.f * (qx * qz - qw * qy);
        float R21 = 2.f * (qy * qz + qw * qx);
        float R22 = 1.f - 2.f * (qx * qx + qy * qy);

        float an = area[n];
        float coef = 2.f * an * invNK;
        float gx = 0.f, gy = 0.f, gz = 0.f, es = 0.f;
        float4* gb4 = ((float4*)d_gflat) + (size_t)b * Nx;
#pragma unroll
        for (int k = 0; k < Kx; k++) {
            float w = wk[k];
            if (w != 0.f) {
                float dx = sh[(k * 6 + 0) * 128 + t], dy = sh[(k * 6 + 1) * 128 + t], dz = sh[(k * 6 + 2) * 128 + t];
                float cx = sh[(k * 6 + 3) * 128 + t], cy = sh[(k * 6 + 4) * 128 + t], cz = sh[(k * 6 + 5) * 128 + t];
                float r0 = cx - (R00 * dx + R01 * dy + R02 * dz);
                float r1 = cy - (R10 * dx + R11 * dy + R12 * dz);
                float r2 = cz - (R20 * dx + R21 * dy + R22 * dz);
                es += w * (r0 * r0 + r1 * r1 + r2 * r2);
                float g0 = coef * w * r0, g1 = coef * w * r1, g2 = coef * w * r2;
                gx += g0; gy += g1; gz += g2;
                atomicAdd(&gb4[jk[k]], make_float4(-g0, -g1, -g2, 0.f));
            }
        }
        atomicAdd(&gb4[n], make_float4(gx, gy, gz, 0.f));
        ev = an * es * invNK;
    }
#pragma unroll
    for (int off = 16; off > 0; off >>= 1) ev += __shfl_xor_sync(0xFFFFFFFFu, ev, off);
    if (lane == 0) atomicAdd(&out[b], ev);
}

// ---------------- pack g pairs [j][p] for the backward GEMM ----------------
__global__ void k_gpack() {
    int idx = blockIdx.x * 256 + threadIdx.x;
    if (idx >= NOx * 8) return;
    int j = idx >> 3, p = idx & 7;
    int n = j / 3, c = j - 3 * n;
    float v0 = d_gflat[((size_t)(2 * p) * Nx + n) * 4 + c];
    float v1 = d_gflat[((size_t)(2 * p + 1) * Nx + n) * 4 + c];
    d_gpk[idx] = pack2(v0, v1);
}

// ---------------- g_h = g_flat @ W2^T: lane owns 2 consecutive j (contiguous 128B g) ----------------
__global__ void __launch_bounds__(256, 2) k_gh(const float* __restrict__ W2) {
    int t = threadIdx.x;
    int lane = t & 31, wrp = t >> 5;
    int k0 = blockIdx.x * 32 + wrp * 4;
    ull acc[4][8];
#pragma unroll
    for (int u = 0; u < 4; u++)
#pragma unroll
        for (int p = 0; p < 8; p++) acc[u][p] = 0ull;

#pragma unroll 1
    for (int pb = blockIdx.y * 32; pb < NP2; pb += gridDim.y * 32) {
        int pr = pb + lane;              // j-pair index; j0 = 2*pr
        bool valid = pr < NP2;
        int prc = min(pr, NP2 - 1);
        // 16 packed g ulls for (j0, j1), contiguous 128 B per lane, warp-contiguous 4 KB
        const ulonglong2* gp = (const ulonglong2*)(d_gpk + (size_t)prc * 16);
        ull g[16];
#pragma unroll
        for (int i = 0; i < 8; i++) { ulonglong2 v = gp[i]; g[2 * i] = v.x; g[2 * i + 1] = v.y; }
        // W2 columns j0, j1 for 4 k-rows: coalesced LDG.64
        float2 w[4];
#pragma unroll
        for (int u = 0; u < 4; u++) {
            float2 val = ((const float2*)(W2 + (size_t)(k0 + u) * NOx))[prc];
            w[u].x = valid ? val.x : 0.f;
            w[u].y = valid ? val.y : 0.f;
        }
#pragma unroll
        for (int u = 0; u < 4; u++) {
            ull w0 = pack2(w[u].x, w[u].x);
            ull w1 = pack2(w[u].y, w[u].y);
#pragma unroll
            for (int p = 0; p < 8; p++) {
                acc[u][p] = ffma2(g[p], w0, acc[u][p]);
                acc[u][p] = ffma2(g[8 + p], w1, acc[u][p]);
            }
        }
    }
#pragma unroll
    for (int u = 0; u < 4; u++)
#pragma unroll
        for (int p = 0; p < 8; p++) {
            float x, y;
            unpack2(acc[u][p], x, y);
#pragma unroll
            for (int off = 16; off > 0; off >>= 1) {
                x += __shfl_xor_sync(0xFFFFFFFFu, x, off);
                y += __shfl_xor_sync(0xFFFFFFFFu, y, off);
            }
            if (lane == 0) {
                atomicAdd(&d_ghid[(2 * p) * Hx + k0 + u], x);
                atomicAdd(&d_ghid[(2 * p + 1) * Hx + k0 + u], y);
            }
        }
}

// ---------------- code_grad = (g_h * relu') @ W1^T ----------------
__global__ void __launch_bounds__(256) k_cgrad(float* __restrict__ out) {
    __shared__ float mg[128];
    int b = blockIdx.x, hg = blockIdx.y, t = threadIdx.x;
    if (t < 128) {
        int h = hg * 128 + t;
        mg[t] = d_ghid[b * Hx + h] * (d_h[h * Bx + b] > 0.f ? 1.f : 0.f);
    }
    __syncthreads();
    float acc = 0.f;
#pragma unroll 8
    for (int hh = 0; hh < 128; hh++) acc += mg[hh] * d_w1t[(hg * 128 + hh) * Lx + t];
    atomicAdd(&out[Bx + b * Lx + t], acc);
}

// ---------------- launch ----------------
extern "C" void kernel_launch(void* const* d_in, const int* in_sizes, int n_in,
                              void* d_out, int out_size) {
    const float* code = (const float*)d_in[0];
    const float* W1   = (const float*)d_in[1];
    const float* b1   = (const float*)d_in[2];
    const float* W2   = (const float*)d_in[3];
    const float* b2   = (const float*)d_in[4];
    const float* xyz  = (const float*)d_in[5];
    const float* wmat = (const float*)d_in[6];
    const float* area = (const float*)d_in[7];
    const int*   nbr  = (const int*)d_in[8];
    const int*   nnb  = (const int*)d_in[9];
    float* out = (float*)d_out;

    k_prep<<<4 + (Bx * Nx * 4 + 255) / 256, 256>>>(code, W1, b1, xyz, out);
    k_recon<<<dim3(4, 74), 256>>>(W2);
    k_comb<<<(Bx * Nx + 255) / 256, 256>>>(b2);
    k_arap<<<dim3((Nx + 127) / 128, Bx), 128>>>(wmat, area, nbr, nnb, out);
    k_gpack<<<(NOx * 8 + 255) / 256, 256>>>();
    k_gh<<<dim3(32, 9), 256>>>(W2);
    k_cgrad<<<dim3(Bx, 8), 256>>>(out);
    (void)in_sizes; (void)n_in; (void)out_size;
}

// round 17
// speedup vs baseline: 1.2235x; 1.1254x over previous
#include <cuda_runtime.h>

#define Bx 16
#define Nx 20000
#define Kx 16
#define Lx 256
#define Hx 1024
#define NOx 60000
#define NQ (NOx / 4)    // 15000 float4 per W2 row
#define NP2 (NOx / 2)   // 30000 j-pairs

typedef unsigned long long ull;

// ---------------- device scratch ----------------
__device__ float d_h[Hx * Bx];                 // hidden post-relu, [k*16+b]
__device__ float d_rflat[4 * Bx * NOx];        // recon partials [ky][b][j]
__device__ __align__(256) float d_xr[Bx * Nx * 8];  // packed {x,y,z,0, rx,ry,rz,0}
__device__ float d_gflat[Bx * Nx * 4];         // grad wrt recon [b][n][4]
__device__ __align__(256) ull d_gpk[8 * NOx];  // packed g pairs, PLANE-major [p][j]
__device__ float d_ghid[Bx * Hx];              // [b][k]
__device__ float d_w1t[Hx * Lx];               // W1^T [h][l]

// ---------------- packed f32x2 helpers ----------------
static __device__ __forceinline__ ull pack2(float x, float y) {
    ull r;
    asm("mov.b64 %0,{%1,%2};" : "=l"(r) : "r"(__float_as_uint(x)), "r"(__float_as_uint(y)));
    return r;
}
static __device__ __forceinline__ void unpack2(ull v, float& x, float& y) {
    unsigned lo, hi;
    asm("mov.b64 {%0,%1},%2;" : "=r"(lo), "=r"(hi) : "l"(v));
    x = __uint_as_float(lo); y = __uint_as_float(hi);
}
static __device__ __forceinline__ ull ffma2(ull a, ull b, ull c) {
    ull d;
    asm("fma.rn.f32x2 %0,%1,%2,%3;" : "=l"(d) : "l"(a), "l"(b), "l"(c));
    return d;
}
// Blackwell 256-bit load
static __device__ __forceinline__ void ldg256(const float* p, float4& a, float4& b) {
    asm volatile("ld.global.v8.f32 {%0,%1,%2,%3,%4,%5,%6,%7},[%8];"
                 : "=f"(a.x), "=f"(a.y), "=f"(a.z), "=f"(a.w),
                   "=f"(b.x), "=f"(b.y), "=f"(b.z), "=f"(b.w)
                 : "l"(p));
}

// ---------------- prep + hidden fused (blocks 0..3 = hidden GEMM) ----------------
__global__ void __launch_bounds__(256) k_prep(const float* __restrict__ code,
                                              const float* __restrict__ W1,
                                              const float* __restrict__ b1,
                                              const float* __restrict__ xyz,
                                              float* __restrict__ out) {
    int t = threadIdx.x;
    if (blockIdx.x < 4) {
        __shared__ float cs[Bx * Lx];
        for (int i = t; i < Bx * Lx; i += 256) cs[i] = code[i];
        __syncthreads();
        int j = blockIdx.x * 256 + t;
        float acc[Bx];
        float bj = b1[j];
#pragma unroll
        for (int b = 0; b < Bx; b++) acc[b] = bj;
#pragma unroll 8
        for (int l = 0; l < Lx; l++) {
            float w = W1[l * Hx + j];
#pragma unroll
            for (int b = 0; b < Bx; b++) acc[b] += cs[b * Lx + l] * w;
        }
#pragma unroll
        for (int b = 0; b < Bx; b++) d_h[j * Bx + b] = fmaxf(acc[b], 0.f);
        return;
    }
    int i = (blockIdx.x - 4) * 256 + t;
    if (i < Bx * Nx * 4) d_gflat[i] = 0.f;
    if (i < Bx * Nx) {
        float4 v;
        v.x = xyz[i * 3 + 0]; v.y = xyz[i * 3 + 1]; v.z = xyz[i * 3 + 2]; v.w = 0.f;
        ((float4*)d_xr)[i * 2] = v;
    }
    if (i < Lx * Hx) { int l = i >> 10, h = i & 1023; d_w1t[h * Lx + l] = W1[i]; }
    if (i < Bx * Hx) d_ghid[i] = 0.f;
    if (i < Bx + Bx * Lx) out[i] = 0.f;
}

// ---------------- recon partials: grid (4 ky, 74 q-blocks), exact work ----------------
__global__ void __launch_bounds__(256, 2) k_recon(const float* __restrict__ W2) {
    __shared__ __align__(16) float hs[256 * 16];  // 16 KB h chunk [k][b]
    int t = threadIdx.x;
    int ky = blockIdx.x;
    for (int i = t; i < 256 * 16; i += 256) hs[i] = d_h[ky * 256 * 16 + i];
    __syncthreads();
    int q = blockIdx.y * 256 + t;
    if (q >= NQ) return;
    const ulonglong2* hu = (const ulonglong2*)hs;
    const float4* wq = ((const float4*)W2) + (size_t)(ky * 256) * NQ;
    ull acc[4][8];
#pragma unroll
    for (int jj = 0; jj < 4; jj++)
#pragma unroll
        for (int p = 0; p < 8; p++) acc[jj][p] = 0ull;

    for (int k4 = 0; k4 < 256; k4 += 4) {
        float4 w[4];
#pragma unroll
        for (int u = 0; u < 4; u++) w[u] = wq[(size_t)(k4 + u) * NQ + q];
#pragma unroll
        for (int u = 0; u < 4; u++) {
            int k = k4 + u;
            ulonglong2 ha = hu[k * 4 + 0], hb = hu[k * 4 + 1];
            ulonglong2 hc = hu[k * 4 + 2], hd = hu[k * 4 + 3];
            ull hv[8] = {ha.x, ha.y, hb.x, hb.y, hc.x, hc.y, hd.x, hd.y};
            ull w0 = pack2(w[u].x, w[u].x), w1 = pack2(w[u].y, w[u].y);
            ull w2v = pack2(w[u].z, w[u].z), w3 = pack2(w[u].w, w[u].w);
#pragma unroll
            for (int p = 0; p < 8; p++) {
                acc[0][p] = ffma2(hv[p], w0, acc[0][p]);
                acc[1][p] = ffma2(hv[p], w1, acc[1][p]);
                acc[2][p] = ffma2(hv[p], w2v, acc[2][p]);
                acc[3][p] = ffma2(hv[p], w3, acc[3][p]);
            }
        }
    }
    float* base = d_rflat + (size_t)ky * Bx * NOx + 4 * q;
#pragma unroll
    for (int p = 0; p < 8; p++) {
        float x0, y0, x1, y1, x2, y2, x3, y3;
        unpack2(acc[0][p], x0, y0);
        unpack2(acc[1][p], x1, y1);
        unpack2(acc[2][p], x2, y2);
        unpack2(acc[3][p], x3, y3);
        *(float4*)(base + (size_t)(2 * p) * NOx)     = make_float4(x0, x1, x2, x3);
        *(float4*)(base + (size_t)(2 * p + 1) * NOx) = make_float4(y0, y1, y2, y3);
    }
}

// ---------------- combine flat partials + bias -> packed xr slots 4..7 ----------------
__global__ void k_comb(const float* __restrict__ b2) {
    int i = blockIdx.x * 256 + threadIdx.x;  // b*Nx + n
    if (i >= Bx * Nx) return;
    int b = i / Nx, n = i - b * Nx;
    float x = 0.f, y = 0.f, z = 0.f;
#pragma unroll
    for (int ky = 0; ky < 4; ky++) {
        const float* p = d_rflat + (size_t)(ky * Bx + b) * NOx + 3 * n;
        x += p[0]; y += p[1]; z += p[2];
    }
    float4 r;
    r.x = x + b2[n * 3 + 0];
    r.y = y + b2[n * 3 + 1];
    r.z = z + b2[n * 3 + 2];
    r.w = 0.f;
    ((float4*)d_xr)[i * 2 + 1] = r;
}

// ---------------- Jacobi rotation on symmetric 4x4, compile-time (P,Q) ----------------
template <int P, int Q>
static __device__ __forceinline__ void jrot(float a[4][4], float v[4][4]) {
    float apq = a[P][Q];
    if (apq != 0.f) {
        float theta = __fdividef(0.5f * (a[Q][Q] - a[P][P]), apq);
        float tt = __fdividef(copysignf(1.f, theta), fabsf(theta) + sqrtf(theta * theta + 1.f));
        float c = rsqrtf(tt * tt + 1.f);
        float s = tt * c;
        a[P][P] -= tt * apq;
        a[Q][Q] += tt * apq;
        a[P][Q] = 0.f; a[Q][P] = 0.f;
#pragma unroll
        for (int r = 0; r < 4; r++) {
            if (r == P || r == Q) continue;
            float arp = a[r][P], arq = a[r][Q];
            float nrp = c * arp - s * arq;
            float nrq = s * arp + c * arq;
            a[r][P] = nrp; a[P][r] = nrp;
            a[r][Q] = nrq; a[Q][r] = nrq;
        }
#pragma unroll
        for (int r = 0; r < 4; r++) {
            float vrp = v[r][P], vrq = v[r][Q];
            v[r][P] = c * vrp - s * vrq;
            v[r][Q] = s * vrp + c * vrq;
        }
    }
}

// ---------------- fused per-vertex ARAP: v8 gathers, shuffle energy reduce ----------------
__global__ void __launch_bounds__(128, 4) k_arap(const float* __restrict__ wmat,
                                                 const float* __restrict__ area,
                                                 const int* __restrict__ nbr,
                                                 const int* __restrict__ numnb,
                                                 float* __restrict__ out) {
    __shared__ float sh[96 * 128];  // [slot][tid]: 6 floats per nbr, 16 nbrs = 48 KB
    const float invNK = 1.f / (float)(Nx * Kx);
    int t = threadIdx.x;
    int lane = t & 31;
    int n = blockIdx.x * 128 + t;
    int b = blockIdx.y;
    float ev = 0.f;
    if (n < Nx) {
        const float* xrb = d_xr + (size_t)b * Nx * 8;
        float4 xn, rn;
        ldg256(xrb + 8 * n, xn, rn);
        int nn = numnb[n];
        const int4* nb4 = (const int4*)(nbr + n * Kx);
        const float4* wm4 = (const float4*)(wmat + n * Kx);
        int jk[Kx]; float wk[Kx];
#pragma unroll
        for (int q = 0; q < 4; q++) {
            int4 jv = nb4[q]; float4 wv = wm4[q];
            jk[q * 4 + 0] = jv.x; jk[q * 4 + 1] = jv.y; jk[q * 4 + 2] = jv.z; jk[q * 4 + 3] = jv.w;
            wk[q * 4 + 0] = (q * 4 + 0 < nn) ? wv.x : 0.f;
            wk[q * 4 + 1] = (q * 4 + 1 < nn) ? wv.y : 0.f;
            wk[q * 4 + 2] = (q * 4 + 2 < nn) ? wv.z : 0.f;
            wk[q * 4 + 3] = (q * 4 + 3 < nn) ? wv.w : 0.f;
        }
        float S00 = 0, S01 = 0, S02 = 0, S10 = 0, S11 = 0, S12 = 0, S20 = 0, S21 = 0, S22 = 0;
#pragma unroll
        for (int k = 0; k < Kx; k++) {
            float w = wk[k];
            if (w != 0.f) {
                int j = jk[k];
                float4 xj, rj;
                ldg256(xrb + 8 * j, xj, rj);
                float dx = xn.x - xj.x, dy = xn.y - xj.y, dz = xn.z - xj.z;
                float cx = rn.x - rj.x, cy = rn.y - rj.y, cz = rn.z - rj.z;
                sh[(k * 6 + 0) * 128 + t] = dx; sh[(k * 6 + 1) * 128 + t] = dy; sh[(k * 6 + 2) * 128 + t] = dz;
                sh[(k * 6 + 3) * 128 + t] = cx; sh[(k * 6 + 4) * 128 + t] = cy; sh[(k * 6 + 5) * 128 + t] = cz;
                S00 += w * dx * cx; S01 += w * dx * cy; S02 += w * dx * cz;
                S10 += w * dy * cx; S11 += w * dy * cy; S12 += w * dy * cz;
                S20 += w * dz * cx; S21 += w * dz * cy; S22 += w * dz * cz;
            }
        }
        float a[4][4], v[4][4];
        a[0][0] = S00 + S11 + S22;
        a[1][1] = S00 - S11 - S22;
        a[2][2] = S11 - S00 - S22;
        a[3][3] = S22 - S00 - S11;
        a[0][1] = a[1][0] = S12 - S21;
        a[0][2] = a[2][0] = S20 - S02;
        a[0][3] = a[3][0] = S01 - S10;
        a[1][2] = a[2][1] = S01 + S10;
        a[1][3] = a[3][1] = S02 + S20;
        a[2][3] = a[3][2] = S12 + S21;
#pragma unroll
        for (int i = 0; i < 4; i++)
#pragma unroll
            for (int j2 = 0; j2 < 4; j2++) v[i][j2] = (i == j2) ? 1.f : 0.f;
#pragma unroll
        for (int sw = 0; sw < 4; sw++) {
            jrot<0, 1>(a, v); jrot<0, 2>(a, v); jrot<0, 3>(a, v);
            jrot<1, 2>(a, v); jrot<1, 3>(a, v); jrot<2, 3>(a, v);
        }
        float best = a[0][0];
        float qw = v[0][0], qx = v[1][0], qy = v[2][0], qz = v[3][0];
#pragma unroll
        for (int m = 1; m < 4; m++)
            if (a[m][m] > best) {
                best = a[m][m];
                qw = v[0][m]; qx = v[1][m]; qy = v[2][m]; qz = v[3][m];
            }
        float inv = rsqrtf(qw * qw + qx * qx + qy * qy + qz * qz);
        qw *= inv; qx *= inv; qy *= inv; qz *= inv;
        float R00 = 1.f - 2.f * (qy * qy + qz * qz);
        float R01 = 2.f * (qx * qy - qw * qz);
        float R02 = 2.f * (qx * qz + qw * qy);
        float R10 = 2.f * (qx * qy + qw * qz);
        float R11 = 1.f - 2.f * (qx * qx + qz * qz);
        float R12 = 2.f * (qy * qz - qw * qx);
        float R20 = 2.f * (qx * qz - qw * qy);
        float R21 = 2.f * (qy * qz + qw * qx);
        float R22 = 1.f - 2.f * (qx * qx + qy * qy);

        float an = area[n];
        float coef = 2.f * an * invNK;
        float gx = 0.f, gy = 0.f, gz = 0.f, es = 0.f;
        float4* gb4 = ((float4*)d_gflat) + (size_t)b * Nx;
#pragma unroll
        for (int k = 0; k < Kx; k++) {
            float w = wk[k];
            if (w != 0.f) {
                float dx = sh[(k * 6 + 0) * 128 + t], dy = sh[(k * 6 + 1) * 128 + t], dz = sh[(k * 6 + 2) * 128 + t];
                float cx = sh[(k * 6 + 3) * 128 + t], cy = sh[(k * 6 + 4) * 128 + t], cz = sh[(k * 6 + 5) * 128 + t];
                float r0 = cx - (R00 * dx + R01 * dy + R02 * dz);
                float r1 = cy - (R10 * dx + R11 * dy + R12 * dz);
                float r2 = cz - (R20 * dx + R21 * dy + R22 * dz);
                es += w * (r0 * r0 + r1 * r1 + r2 * r2);
                float g0 = coef * w * r0, g1 = coef * w * r1, g2 = coef * w * r2;
                gx += g0; gy += g1; gz += g2;
                atomicAdd(&gb4[jk[k]], make_float4(-g0, -g1, -g2, 0.f));
            }
        }
        atomicAdd(&gb4[n], make_float4(gx, gy, gz, 0.f));
        ev = an * es * invNK;
    }
#pragma unroll
    for (int off = 16; off > 0; off >>= 1) ev += __shfl_xor_sync(0xFFFFFFFFu, ev, off);
    if (lane == 0) atomicAdd(&out[b], ev);
}

// ---------------- pack g pairs PLANE-major [p][j] for the backward GEMM ----------------
__global__ void k_gpack() {
    int j = blockIdx.x * 256 + threadIdx.x;
    int p = blockIdx.y;
    if (j >= NOx) return;
    int n = j / 3, c = j - 3 * n;
    float v0 = d_gflat[((size_t)(2 * p) * Nx + n) * 4 + c];
    float v1 = d_gflat[((size_t)(2 * p + 1) * Nx + n) * 4 + c];
    d_gpk[(size_t)p * NOx + j] = pack2(v0, v1);
}

// ---------------- g_h = g_flat @ W2^T: plane-major g, all loads coalesced ----------------
__global__ void __launch_bounds__(256, 2) k_gh(const float* __restrict__ W2) {
    int t = threadIdx.x;
    int lane = t & 31, wrp = t >> 5;
    int k0 = blockIdx.x * 32 + wrp * 4;
    ull acc[4][8];
#pragma unroll
    for (int u = 0; u < 4; u++)
#pragma unroll
        for (int p = 0; p < 8; p++) acc[u][p] = 0ull;

#pragma unroll 1
    for (int pb = blockIdx.y * 32; pb < NP2; pb += gridDim.y * 32) {
        int pr = pb + lane;                 // j-pair index; j0 = 2*pr, j1 = 2*pr+1
        bool valid = pr < NP2;
        int prc = min(pr, NP2 - 1);
        // 8 plane loads: lane stride 16 B -> perfectly coalesced LDG.128
        ull gj0[8], gj1[8];
#pragma unroll
        for (int p = 0; p < 8; p++) {
            ulonglong2 v = ((const ulonglong2*)(d_gpk + (size_t)p * NOx))[prc];
            gj0[p] = v.x; gj1[p] = v.y;
        }
        // W2 columns (j0, j1) for 4 k-rows: coalesced LDG.64
        float2 w[4];
#pragma unroll
        for (int u = 0; u < 4; u++) {
            float2 val = ((const float2*)(W2 + (size_t)(k0 + u) * NOx))[prc];
            w[u].x = valid ? val.x : 0.f;
            w[u].y = valid ? val.y : 0.f;
        }
#pragma unroll
        for (int u = 0; u < 4; u++) {
            ull w0 = pack2(w[u].x, w[u].x);
            ull w1 = pack2(w[u].y, w[u].y);
#pragma unroll
            for (int p = 0; p < 8; p++) {
                acc[u][p] = ffma2(gj0[p], w0, acc[u][p]);
                acc[u][p] = ffma2(gj1[p], w1, acc[u][p]);
            }
        }
    }
#pragma unroll
    for (int u = 0; u < 4; u++)
#pragma unroll
        for (int p = 0; p < 8; p++) {
            float x, y;
            unpack2(acc[u][p], x, y);
#pragma unroll
            for (int off = 16; off > 0; off >>= 1) {
                x += __shfl_xor_sync(0xFFFFFFFFu, x, off);
                y += __shfl_xor_sync(0xFFFFFFFFu, y, off);
            }
            if (lane == 0) {
                atomicAdd(&d_ghid[(2 * p) * Hx + k0 + u], x);
                atomicAdd(&d_ghid[(2 * p + 1) * Hx + k0 + u], y);
            }
        }
}

// ---------------- code_grad = (g_h * relu') @ W1^T ----------------
__global__ void __launch_bounds__(256) k_cgrad(float* __restrict__ out) {
    __shared__ float mg[128];
    int b = blockIdx.x, hg = blockIdx.y, t = threadIdx.x;
    if (t < 128) {
        int h = hg * 128 + t;
        mg[t] = d_ghid[b * Hx + h] * (d_h[h * Bx + b] > 0.f ? 1.f : 0.f);
    }
    __syncthreads();
    float acc = 0.f;
#pragma unroll 8
    for (int hh = 0; hh < 128; hh++) acc += mg[hh] * d_w1t[(hg * 128 + hh) * Lx + t];
    atomicAdd(&out[Bx + b * Lx + t], acc);
}

// ---------------- launch ----------------
extern "C" void kernel_launch(void* const* d_in, const int* in_sizes, int n_in,
                              void* d_out, int out_size) {
    const float* code = (const float*)d_in[0];
    const float* W1   = (const float*)d_in[1];
    const float* b1   = (const float*)d_in[2];
    const float* W2   = (const float*)d_in[3];
    const float* b2   = (const float*)d_in[4];
    const float* xyz  = (const float*)d_in[5];
    const float* wmat = (const float*)d_in[6];
    const float* area = (const float*)d_in[7];
    const int*   nbr  = (const int*)d_in[8];
    const int*   nnb  = (const int*)d_in[9];
    float* out = (float*)d_out;

    k_prep<<<4 + (Bx * Nx * 4 + 255) / 256, 256>>>(code, W1, b1, xyz, out);
    k_recon<<<dim3(4, 74), 256>>>(W2);
    k_comb<<<(Bx * Nx + 255) / 256, 256>>>(b2);
    k_arap<<<dim3((Nx + 127) / 128, Bx), 128>>>(wmat, area, nbr, nnb, out);
    k_gpack<<<dim3((NOx + 255) / 256, 8), 256>>>();
    k_gh<<<dim3(32, 9), 256>>>(W2);
    k_cgrad<<<dim3(Bx, 8), 256>>>(out);
    (void)in_sizes; (void)n_in; (void)out_size;
}